// round 5
// baseline (speedup 1.0000x reference)
#include <cuda_runtime.h>
#include <cuda_bf16.h>
#include <math.h>
#include <stdint.h>

// ---------------- problem constants ----------------
#define NT      32768
#define NPER    2048
#define IN_C    256
#define DIM     128
#define H1DIM   256
#define NATOMS  20
#define ENC_H   100
#define OUTC    6
#define MASK_WORDS (NT * 64)
#define TAU     1.5e-3f

typedef unsigned long long ull;

// ---------------- scratch ----------------
__device__ unsigned g_mask[MASK_WORDS];
__device__ float    g_stats[2 * IN_C];
__device__ int      g_ids[NT];
__device__ int      g_flag[NT];
__device__ int      g_nflag;
__device__ float    g_b1f[H1DIM];
__device__ float    g_W1f[IN_C * H1DIM];
__device__ float    g_TW[NATOMS * DIM];
__device__ float    g_A1p[128 * 128];
__device__ float    g_a1p[128];
__device__ float    g_h1[(size_t)NT * H1DIM];
__device__ float    g_h2[(size_t)NT * DIM];
__device__ float    g_t1[(size_t)NT * 128];

// ---------------- helpers ----------------
__device__ __forceinline__ float gelu(float x) {
    return 0.5f * x * (1.0f + erff(x * 0.70710678118654752f));
}
__device__ __forceinline__ ull pk2(float lo, float hi) {
    ull r; asm("mov.b64 %0, {%1, %2};" : "=l"(r) : "f"(lo), "f"(hi)); return r;
}
__device__ __forceinline__ void fma2(ull& d, ull a, ull b) {
    asm("fma.rn.f32x2 %0, %1, %2, %0;" : "+l"(d) : "l"(a), "l"(b));
}
__device__ __forceinline__ float2 upk(ull v) {
    float2 f; asm("mov.b64 {%0, %1}, %2;" : "=f"(f.x), "=f"(f.y) : "l"(v)); return f;
}

// ---------------- K0: zero mask + stats + flag counter ----------------
__global__ void k_zero() {
    int i = blockIdx.x * blockDim.x + threadIdx.x;
    if (i < MASK_WORDS) g_mask[i] = 0u;
    if (i < 2 * IN_C)   g_stats[i] = 0.0f;
    if (i == 0)         g_nflag = 0;
}

// ---------------- K1: BN stats ----------------
__global__ void k_bn_stats(const float* __restrict__ x) {
    int c  = threadIdx.x;
    int r0 = blockIdx.x * 128;
    float s = 0.f, q = 0.f;
    #pragma unroll 4
    for (int r = 0; r < 128; r++) {
        float v = x[(size_t)(r0 + r) * IN_C + c];
        s += v; q += v * v;
    }
    atomicAdd(&g_stats[c], s);
    atomicAdd(&g_stats[IN_C + c], q);
}

// ---------------- K2: fold BN into W1 ----------------
__global__ void k_fold(const float* __restrict__ W1, const float* __restrict__ b1,
                       const float* __restrict__ gamma, const float* __restrict__ beta) {
    int j = blockIdx.x;      // output col
    int c = threadIdx.x;     // input channel
    float mean = g_stats[c] * (1.0f / NT);
    float var  = g_stats[IN_C + c] * (1.0f / NT) - mean * mean;
    float inv  = rsqrtf(var + 1e-5f);
    float sc   = gamma[c] * inv;
    float sh   = beta[c] - mean * sc;
    float w    = W1[c * H1DIM + j];
    g_W1f[c * H1DIM + j] = sc * w;
    __shared__ float red[256];
    red[c] = sh * w;
    __syncthreads();
    for (int o = 128; o > 0; o >>= 1) {
        if (c < o) red[c] += red[c + o];
        __syncthreads();
    }
    if (c == 0) g_b1f[j] = b1[j] + red[0];
}

// ---------------- K3: TW = embed[0:20] @ W_msg (warp per output) ----------------
__global__ void k_tw2(const float* __restrict__ embed, const float* __restrict__ Wm) {
    int w = (blockIdx.x * blockDim.x + threadIdx.x) >> 5;
    int lane = threadIdx.x & 31;
    if (w < NATOMS * DIM) {
        int a = w >> 7, j = w & 127;
        float s = 0.f;
        #pragma unroll
        for (int i = 0; i < 4; i++) {
            int k = lane * 4 + i;
            s += embed[a * DIM + k] * Wm[k * DIM + j];
        }
        #pragma unroll
        for (int o = 16; o > 0; o >>= 1) s += __shfl_xor_sync(0xffffffffu, s, o);
        if (lane == 0) g_TW[w] = s;
    }
}

// ---------------- K3b: pad A1 (128x100 -> 128x128) ----------------
__global__ void k_padA1(const float* __restrict__ A1, const float* __restrict__ a1) {
    int t = blockIdx.x * blockDim.x + threadIdx.x;
    if (t < 128 * 128) {
        int k = t >> 7, j = t & 127;
        g_A1p[t] = (j < ENC_H) ? A1[k * ENC_H + j] : 0.0f;
        if (k == 0) g_a1p[j] = (j < ENC_H) ? a1[j] : 0.0f;
    }
}

// ---------------- K4: edge scatter ----------------
__global__ void k_edges(const int* __restrict__ ei, int E) {
    int e = blockIdx.x * blockDim.x + threadIdx.x;
    if (e < E) {
        int s = ei[e];
        int d = ei[E + e];
        if ((s >> 11) == (d >> 11)) {
            unsigned bit = ((unsigned)s << 11) + (unsigned)(d & (NPER - 1));
            atomicOr(&g_mask[bit >> 5], 1u << (bit & 31));
        }
    }
}

// ---------------- f32x2 SGEMM + bias + gelu (BM=BN=128, BK=16, TM=8, TN=8) ----------------
__global__ void __launch_bounds__(256)
k_sgemm_gelu(const float* __restrict__ A, const float* __restrict__ B,
             const float* __restrict__ bias, float* __restrict__ C,
             int K, int N) {
    __shared__ float As[16 * 128];
    __shared__ float Bs[16 * 128];
    int tid = threadIdx.x;
    const float* Ab = A + (size_t)blockIdx.y * 128 * K;
    const float* Bb = B + blockIdx.x * 128;
    float*       Cb = C + (size_t)blockIdx.y * 128 * N + blockIdx.x * 128;
    const float* bb = bias + blockIdx.x * 128;

    int arow = tid >> 1, acol = (tid & 1) * 8;
    int brow = tid >> 4, bcol = (tid & 15) * 8;
    int tr = (tid >> 4) * 8, tc = (tid & 15) * 8;

    ull acc[8][4];
    #pragma unroll
    for (int i = 0; i < 8; i++)
        #pragma unroll
        for (int j = 0; j < 4; j++) acc[i][j] = 0ull;

    for (int k0 = 0; k0 < K; k0 += 16) {
        float4 av0 = *(const float4*)(Ab + (size_t)arow * K + k0 + acol);
        float4 av1 = *(const float4*)(Ab + (size_t)arow * K + k0 + acol + 4);
        As[(acol + 0) * 128 + arow] = av0.x;
        As[(acol + 1) * 128 + arow] = av0.y;
        As[(acol + 2) * 128 + arow] = av0.z;
        As[(acol + 3) * 128 + arow] = av0.w;
        As[(acol + 4) * 128 + arow] = av1.x;
        As[(acol + 5) * 128 + arow] = av1.y;
        As[(acol + 6) * 128 + arow] = av1.z;
        As[(acol + 7) * 128 + arow] = av1.w;
        float4 bv0 = *(const float4*)(Bb + (size_t)(k0 + brow) * N + bcol);
        float4 bv1 = *(const float4*)(Bb + (size_t)(k0 + brow) * N + bcol + 4);
        *(float4*)&Bs[brow * 128 + bcol]     = bv0;
        *(float4*)&Bs[brow * 128 + bcol + 4] = bv1;
        __syncthreads();
        #pragma unroll
        for (int kk = 0; kk < 16; kk++) {
            float4 a0 = *(const float4*)&As[kk * 128 + tr];
            float4 a1 = *(const float4*)&As[kk * 128 + tr + 4];
            float4 b0 = *(const float4*)&Bs[kk * 128 + tc];
            float4 b1 = *(const float4*)&Bs[kk * 128 + tc + 4];
            ull ra[8], rb[4];
            ra[0] = pk2(a0.x, a0.x); ra[1] = pk2(a0.y, a0.y);
            ra[2] = pk2(a0.z, a0.z); ra[3] = pk2(a0.w, a0.w);
            ra[4] = pk2(a1.x, a1.x); ra[5] = pk2(a1.y, a1.y);
            ra[6] = pk2(a1.z, a1.z); ra[7] = pk2(a1.w, a1.w);
            rb[0] = pk2(b0.x, b0.y); rb[1] = pk2(b0.z, b0.w);
            rb[2] = pk2(b1.x, b1.y); rb[3] = pk2(b1.z, b1.w);
            #pragma unroll
            for (int i = 0; i < 8; i++)
                #pragma unroll
                for (int j = 0; j < 4; j++)
                    fma2(acc[i][j], ra[i], rb[j]);
        }
        __syncthreads();
    }
    #pragma unroll
    for (int i = 0; i < 8; i++) {
        int row = tr + i;
        float o[8];
        #pragma unroll
        for (int j = 0; j < 4; j++) {
            float2 f = upk(acc[i][j]);
            o[2 * j + 0] = gelu(f.x + bb[tc + 2 * j + 0]);
            o[2 * j + 1] = gelu(f.y + bb[tc + 2 * j + 1]);
        }
        *(float4*)(Cb + (size_t)row * N + tc)     = make_float4(o[0], o[1], o[2], o[3]);
        *(float4*)(Cb + (size_t)row * N + tc + 4) = make_float4(o[4], o[5], o[6], o[7]);
    }
}

// ---------------- K7: logits + argmax + near-tie flag ----------------
__global__ void __launch_bounds__(256)
k_logits_argmax(const float* __restrict__ W3, const float* __restrict__ b3) {
    __shared__ float rows[64][129];
    __shared__ float W3s[128 * NATOMS];
    __shared__ float b3s[NATOMS];
    int tid = threadIdx.x;
    int rbase = blockIdx.x * 64;
    const float* src = g_h2 + (size_t)rbase * DIM;
    for (int i = tid; i < 64 * 128; i += 256) rows[i >> 7][i & 127] = src[i];
    for (int i = tid; i < 128 * NATOMS; i += 256) W3s[i] = W3[i];
    if (tid < NATOMS) b3s[tid] = b3[tid];
    __syncthreads();

    int r = tid >> 2, part = tid & 3;
    float acc[5] = {0, 0, 0, 0, 0};
    for (int k = 0; k < 128; k++) {
        float v = rows[r][k];
        #pragma unroll
        for (int j = 0; j < 5; j++) acc[j] += v * W3s[k * NATOMS + part * 5 + j];
    }
    float b1 = -1e30f, b2 = -1e30f; int i1 = 0;
    #pragma unroll
    for (int j = 0; j < 5; j++) {
        int col = part * 5 + j;
        float lg = acc[j] + b3s[col];
        if (lg > b1) { b2 = b1; b1 = lg; i1 = col; }
        else if (lg > b2) b2 = lg;
    }
    #pragma unroll
    for (int o = 1; o <= 2; o <<= 1) {
        float ob1 = __shfl_xor_sync(0xffffffffu, b1, o);
        int   oi1 = __shfl_xor_sync(0xffffffffu, i1, o);
        float ob2 = __shfl_xor_sync(0xffffffffu, b2, o);
        if (ob1 > b1 || (ob1 == b1 && oi1 < i1)) {
            b2 = fmaxf(b1, ob2); b1 = ob1; i1 = oi1;
        } else {
            b2 = fmaxf(b2, ob1);
        }
    }
    if (part == 0) {
        int node = rbase + r;
        g_ids[node] = i1;
        if (b1 - b2 < TAU) {
            int p = atomicAdd(&g_nflag, 1);
            g_flag[p] = node;
        }
    }
}

// ---------------- K7b: fp32 recompute of flagged nodes ----------------
__global__ void __launch_bounds__(256)
k_fix(const float* __restrict__ x, const float* __restrict__ W2,
      const float* __restrict__ b2, const float* __restrict__ W3,
      const float* __restrict__ b3) {
    __shared__ float xs[256], h1s[256], part[256], h2s[128], lg[NATOMS];
    int tid = threadIdx.x;
    int nf = g_nflag;
    for (int fi = blockIdx.x; fi < nf; fi += gridDim.x) {
        int node = g_flag[fi];
        xs[tid] = x[(size_t)node * IN_C + tid];
        __syncthreads();
        float s = 0.f;
        #pragma unroll 8
        for (int c = 0; c < 256; c++) s += xs[c] * g_W1f[c * H1DIM + tid];
        h1s[tid] = gelu(s + g_b1f[tid]);
        __syncthreads();
        {
            int j = tid & 127, p = tid >> 7;
            float s2 = 0.f;
            #pragma unroll 8
            for (int c = p * 128; c < p * 128 + 128; c++) s2 += h1s[c] * W2[c * DIM + j];
            part[tid] = s2;
        }
        __syncthreads();
        if (tid < 128) h2s[tid] = gelu(part[tid] + part[128 + tid] + b2[tid]);
        __syncthreads();
        if (tid < NATOMS) {
            float s3 = b3[tid];
            #pragma unroll 8
            for (int k = 0; k < 128; k++) s3 += h2s[k] * W3[k * NATOMS + tid];
            lg[tid] = s3;
        }
        __syncthreads();
        if (tid == 0) {
            float best = lg[0]; int bi = 0;
            for (int a = 1; a < NATOMS; a++) if (lg[a] > best) { best = lg[a]; bi = a; }
            g_ids[node] = bi;
        }
        __syncthreads();
    }
}

// ---------------- K8: aggregation -> z, coords ----------------
__global__ void __launch_bounds__(256)
k_agg(const float* __restrict__ b_msg, const float* __restrict__ w_coor,
      const float* __restrict__ coords, float* __restrict__ out_z,
      float* __restrict__ out_coors) {
    __shared__ float TWs[NATOMS * DIM];
    __shared__ float wcs[DIM * 3];
    __shared__ float bms[DIM];
    __shared__ int   hist[8][NATOMS];
    int tid = threadIdx.x;
    for (int i = tid; i < NATOMS * DIM; i += 256) TWs[i] = g_TW[i];
    for (int i = tid; i < DIM * 3; i += 256)      wcs[i] = w_coor[i];
    for (int i = tid; i < DIM; i += 256)          bms[i] = b_msg[i];
    __syncthreads();

    int warp = tid >> 5, lane = tid & 31;
    int* myhist = hist[warp];
    int wglobal = blockIdx.x * 8 + warp;
    int wstride = gridDim.x * 8;
    int d0 = lane * 4;

    for (int node = wglobal; node < NT; node += wstride) {
        if (lane < NATOMS) myhist[lane] = 0;
        __syncwarp();
        int base = node & ~(NPER - 1);
        int deg = 0;
        #pragma unroll
        for (int half = 0; half < 2; half++) {
            int w = lane + half * 32;
            unsigned m = g_mask[(size_t)node * 64 + w];
            deg += __popc(m);
            while (m) {
                int b = __ffs(m) - 1;
                m &= m - 1;
                int id = g_ids[base + w * 32 + b];
                atomicAdd(&myhist[id], 1);
            }
        }
        deg = __reduce_add_sync(0xffffffffu, deg);
        __syncwarp();
        float invdeg = 1.0f / (float)(deg > 0 ? deg : 1);
        int myid = g_ids[node];

        float4 s = make_float4(0.f, 0.f, 0.f, 0.f);
        #pragma unroll
        for (int a = 0; a < NATOMS; a++) {
            float cf = (float)myhist[a];
            float4 t = *(const float4*)&TWs[a * DIM + d0];
            s.x += cf * t.x; s.y += cf * t.y; s.z += cf * t.z; s.w += cf * t.w;
        }
        float4 own = *(const float4*)&TWs[myid * DIM + d0];
        float h0 = gelu(bms[d0 + 0] + own.x + invdeg * s.x);
        float h1 = gelu(bms[d0 + 1] + own.y + invdeg * s.y);
        float h2 = gelu(bms[d0 + 2] + own.z + invdeg * s.z);
        float h3 = gelu(bms[d0 + 3] + own.w + invdeg * s.w);
        *(float4*)&out_z[(size_t)node * DIM + d0] = make_float4(h0, h1, h2, h3);

        float p0 = h0 * wcs[(d0 + 0) * 3 + 0] + h1 * wcs[(d0 + 1) * 3 + 0]
                 + h2 * wcs[(d0 + 2) * 3 + 0] + h3 * wcs[(d0 + 3) * 3 + 0];
        float p1 = h0 * wcs[(d0 + 0) * 3 + 1] + h1 * wcs[(d0 + 1) * 3 + 1]
                 + h2 * wcs[(d0 + 2) * 3 + 1] + h3 * wcs[(d0 + 3) * 3 + 1];
        float p2 = h0 * wcs[(d0 + 0) * 3 + 2] + h1 * wcs[(d0 + 1) * 3 + 2]
                 + h2 * wcs[(d0 + 2) * 3 + 2] + h3 * wcs[(d0 + 3) * 3 + 2];
        #pragma unroll
        for (int o = 16; o > 0; o >>= 1) {
            p0 += __shfl_xor_sync(0xffffffffu, p0, o);
            p1 += __shfl_xor_sync(0xffffffffu, p1, o);
            p2 += __shfl_xor_sync(0xffffffffu, p2, o);
        }
        if (lane == 0) {
            out_coors[(size_t)node * 3 + 0] = coords[(size_t)node * 3 + 0] + tanhf(p0);
            out_coors[(size_t)node * 3 + 1] = coords[(size_t)node * 3 + 1] + tanhf(p1);
            out_coors[(size_t)node * 3 + 2] = coords[(size_t)node * 3 + 2] + tanhf(p2);
        }
    }
}

// ---------------- K10: angles head ----------------
__global__ void __launch_bounds__(256)
k_angles(const float* __restrict__ A2, const float* __restrict__ a2,
         const float* __restrict__ dyt_alpha, const float* __restrict__ dyt_w,
         const float* __restrict__ dyt_b, float* __restrict__ out_angles) {
    __shared__ float rows[64][129];
    __shared__ float A2s[ENC_H * OUTC];
    __shared__ float a2s[OUTC];
    int tid = threadIdx.x;
    int rbase = blockIdx.x * 64;
    const float* src = g_t1 + (size_t)rbase * 128;
    for (int i = tid; i < 64 * 128; i += 256) rows[i >> 7][i & 127] = src[i];
    for (int i = tid; i < ENC_H * OUTC; i += 256) A2s[i] = A2[i];
    if (tid < OUTC) a2s[tid] = a2[tid];
    __syncthreads();

    if (tid < 64) {
        float alpha = dyt_alpha[0];
        float acc[OUTC] = {0, 0, 0, 0, 0, 0};
        for (int k = 0; k < ENC_H; k++) {
            float v = rows[tid][k];
            #pragma unroll
            for (int c = 0; c < OUTC; c++) acc[c] += v * A2s[k * OUTC + c];
        }
        int node = rbase + tid;
        #pragma unroll
        for (int c = 0; c < OUTC; c++) {
            float t = gelu(acc[c] + a2s[c]);
            float u = tanhf(alpha * t) * dyt_w[c] + dyt_b[c];
            out_angles[(size_t)node * OUTC + c] = tanhf(u);
        }
    }
}

// ---------------- launch ----------------
extern "C" void kernel_launch(void* const* d_in, const int* in_sizes, int n_in,
                              void* d_out, int out_size) {
    const float* x_res     = (const float*)d_in[0];
    const float* coords    = (const float*)d_in[1];
    const int*   edge_idx  = (const int*)  d_in[2];
    const float* bn_gamma  = (const float*)d_in[4];
    const float* bn_beta   = (const float*)d_in[5];
    const float* W1        = (const float*)d_in[6];
    const float* b1        = (const float*)d_in[7];
    const float* W2        = (const float*)d_in[8];
    const float* b2        = (const float*)d_in[9];
    const float* W3        = (const float*)d_in[10];
    const float* b3        = (const float*)d_in[11];
    const float* embed     = (const float*)d_in[12];
    const float* W_msg     = (const float*)d_in[13];
    const float* b_msg     = (const float*)d_in[14];
    const float* w_coor    = (const float*)d_in[15];
    const float* A1        = (const float*)d_in[16];
    const float* a1        = (const float*)d_in[17];
    const float* A2        = (const float*)d_in[18];
    const float* a2        = (const float*)d_in[19];
    const float* dyt_alpha = (const float*)d_in[20];
    const float* dyt_w     = (const float*)d_in[21];
    const float* dyt_b     = (const float*)d_in[22];
    int E = in_sizes[2] / 2;

    float* out        = (float*)d_out;
    float* out_angles = out;
    float* out_z      = out + (size_t)NT * OUTC;
    float* out_coors  = out_z + (size_t)NT * DIM;

    float* h1p;  cudaGetSymbolAddress((void**)&h1p,  g_h1);
    float* h2p;  cudaGetSymbolAddress((void**)&h2p,  g_h2);
    float* t1p;  cudaGetSymbolAddress((void**)&t1p,  g_t1);
    float* W1fp; cudaGetSymbolAddress((void**)&W1fp, g_W1f);
    float* b1fp; cudaGetSymbolAddress((void**)&b1fp, g_b1f);
    float* A1pp; cudaGetSymbolAddress((void**)&A1pp, g_A1p);
    float* a1pp; cudaGetSymbolAddress((void**)&a1pp, g_a1p);

    k_zero<<<4096, 512>>>();
    k_bn_stats<<<NT / 128, 256>>>(x_res);
    k_fold<<<H1DIM, IN_C>>>(W1, b1, bn_gamma, bn_beta);
    k_tw2<<<320, 256>>>(embed, W_msg);
    k_padA1<<<64, 256>>>(A1, a1);
    k_edges<<<(E + 255) / 256, 256>>>(edge_idx, E);

    // h1 = gelu(xn @ W1f + b1f)  [32768 x 256]
    k_sgemm_gelu<<<dim3(H1DIM / 128, NT / 128), 256>>>(x_res, W1fp, b1fp, h1p, IN_C, H1DIM);
    // h2 = gelu(h1 @ W2 + b2)    [32768 x 128]
    k_sgemm_gelu<<<dim3(DIM / 128, NT / 128), 256>>>(h1p, W2, b2, h2p, H1DIM, DIM);
    // ids = argmax(h2 @ W3 + b3) + near-tie flags
    k_logits_argmax<<<NT / 64, 256>>>(W3, b3);
    // fp32 recompute of flagged nodes
    k_fix<<<256, 256>>>(x_res, W2, b2, W3, b3);
    // z, coords
    k_agg<<<512, 256>>>(b_msg, w_coor, coords, out_z, out_coors);
    // t1 = gelu(z @ A1p + a1p)   [32768 x 128 padded]
    k_sgemm_gelu<<<dim3(1, NT / 128), 256>>>(out_z, A1pp, a1pp, t1p, DIM, 128);
    // angles
    k_angles<<<NT / 64, 256>>>(A2, a2, dyt_alpha, dyt_w, dyt_b, out_angles);
}

// round 6
// speedup vs baseline: 4.5847x; 4.5847x over previous
#include <cuda_runtime.h>
#include <cuda_bf16.h>
#include <math.h>
#include <stdint.h>

// ---------------- problem constants ----------------
#define NT      32768
#define NPER    2048
#define IN_C    256
#define DIM     128
#define H1DIM   256
#define NATOMS  20
#define ENC_H   100
#define OUTC    6
#define MASK_WORDS (NT * 64)

// ---------------- scratch ----------------
__device__ unsigned g_mask[MASK_WORDS];
__device__ float    g_stats[2 * IN_C];
__device__ int      g_ids[NT];
__device__ float    g_b1f[H1DIM];
__device__ float    g_W1f[IN_C * H1DIM];   // BN-folded W1 (GEMM1 B operand)
__device__ float    g_TW[NATOMS * DIM];
__device__ float    g_A1p[128 * 128];      // A1 zero-padded 100->128 cols
__device__ float    g_a1p[128];
__device__ float    g_h1[(size_t)NT * H1DIM];

// ---------------- helpers ----------------
__device__ __forceinline__ float gelu(float x) {
    return 0.5f * x * (1.0f + erff(x * 0.70710678118654752f));
}

// ---------------- K0: zero mask + stats ----------------
__global__ void k_zero() {
    int i = blockIdx.x * blockDim.x + threadIdx.x;
    if (i < MASK_WORDS) g_mask[i] = 0u;
    if (i < 2 * IN_C)   g_stats[i] = 0.0f;
}

// ---------------- K1: BN stats ----------------
__global__ void k_bn_stats(const float* __restrict__ x) {
    int c  = threadIdx.x;
    int r0 = blockIdx.x * 128;
    float s = 0.f, q = 0.f;
    #pragma unroll 4
    for (int r = 0; r < 128; r++) {
        float v = x[(size_t)(r0 + r) * IN_C + c];
        s += v; q += v * v;
    }
    atomicAdd(&g_stats[c], s);
    atomicAdd(&g_stats[IN_C + c], q);
}

// ---------------- K2: fold BN into W1 ----------------
__global__ void k_fold(const float* __restrict__ W1, const float* __restrict__ b1,
                       const float* __restrict__ gamma, const float* __restrict__ beta) {
    int j = blockIdx.x;      // output col
    int c = threadIdx.x;     // input channel
    float mean = g_stats[c] * (1.0f / NT);
    float var  = g_stats[IN_C + c] * (1.0f / NT) - mean * mean;
    float inv  = rsqrtf(var + 1e-5f);
    float sc   = gamma[c] * inv;
    float sh   = beta[c] - mean * sc;
    float w    = W1[c * H1DIM + j];
    g_W1f[c * H1DIM + j] = sc * w;
    __shared__ float red[256];
    red[c] = sh * w;
    __syncthreads();
    for (int o = 128; o > 0; o >>= 1) {
        if (c < o) red[c] += red[c + o];
        __syncthreads();
    }
    if (c == 0) g_b1f[j] = b1[j] + red[0];
}

// ---------------- K3: TW = embed[0:20] @ W_msg (warp per output) ----------------
__global__ void k_tw2(const float* __restrict__ embed, const float* __restrict__ Wm) {
    int w = (blockIdx.x * blockDim.x + threadIdx.x) >> 5;
    int lane = threadIdx.x & 31;
    if (w < NATOMS * DIM) {
        int a = w >> 7, j = w & 127;
        float s = 0.f;
        #pragma unroll
        for (int i = 0; i < 4; i++) {
            int k = lane * 4 + i;
            s += embed[a * DIM + k] * Wm[k * DIM + j];
        }
        #pragma unroll
        for (int o = 16; o > 0; o >>= 1) s += __shfl_xor_sync(0xffffffffu, s, o);
        if (lane == 0) g_TW[w] = s;
    }
}

// ---------------- K3b: pad A1 (128x100 -> 128x128) ----------------
__global__ void k_padA1(const float* __restrict__ A1, const float* __restrict__ a1) {
    int t = blockIdx.x * blockDim.x + threadIdx.x;
    if (t < 128 * 128) {
        int k = t >> 7, j = t & 127;
        g_A1p[t] = (j < ENC_H) ? A1[k * ENC_H + j] : 0.0f;
        if (k == 0) g_a1p[j] = (j < ENC_H) ? a1[j] : 0.0f;
    }
}

// ---------------- K4: edge scatter ----------------
__global__ void k_edges(const int* __restrict__ ei, int E) {
    int e = blockIdx.x * blockDim.x + threadIdx.x;
    if (e < E) {
        int s = ei[e];
        int d = ei[E + e];
        if ((s >> 11) == (d >> 11)) {
            unsigned bit = ((unsigned)s << 11) + (unsigned)(d & (NPER - 1));
            atomicOr(&g_mask[bit >> 5], 1u << (bit & 31));
        }
    }
}

// ---------------- fused SGEMM (BM=BN=128, BK=16, TM=TN=8) ----------------
// EPI 0: C = gelu(A@B + bias)            (GEMM1 -> g_h1)
// EPI 1: h2 tile -> smem; logits = h2@W3+b3; argmax -> g_ids   (nothing to gmem but ids)
// EPI 2: t1 tile -> smem; t2 = gelu(t1[:,0:100]@A2+a2); dyt; tanh -> OUT angles
template<int EPI>
__global__ void __launch_bounds__(256)
k_gemm(const float* __restrict__ A, const float* __restrict__ B,
       const float* __restrict__ bias, float* __restrict__ C,
       const float* __restrict__ X0, const float* __restrict__ X1,
       const float* __restrict__ X2, const float* __restrict__ X3,
       const float* __restrict__ X4, float* __restrict__ OUT,
       int K, int N) {
    extern __shared__ float sm[];
    float* As   = sm;              // 16*128
    float* Bs   = sm + 2048;       // 16*128
    float* hbuf = sm + 4096;       // 128*129 (EPI 1/2)
    float* aux  = sm + 4096 + 128 * 129;

    int tid = threadIdx.x;
    int nt = blockIdx.x, mt = blockIdx.y;
    const float* Ab = A + (size_t)mt * 128 * K;
    const float* Bb = B + nt * 128;
    const float* bb = bias + nt * 128;

    int arow = tid >> 1, acol = (tid & 1) * 8;
    int brow = tid >> 4, bcol = (tid & 15) * 8;
    int tr = (tid >> 4) * 8, tc = (tid & 15) * 8;

    float acc[8][8];
    #pragma unroll
    for (int i = 0; i < 8; i++)
        #pragma unroll
        for (int j = 0; j < 8; j++) acc[i][j] = 0.f;

    for (int k0 = 0; k0 < K; k0 += 16) {
        float4 av0 = *(const float4*)(Ab + (size_t)arow * K + k0 + acol);
        float4 av1 = *(const float4*)(Ab + (size_t)arow * K + k0 + acol + 4);
        As[(acol + 0) * 128 + arow] = av0.x;
        As[(acol + 1) * 128 + arow] = av0.y;
        As[(acol + 2) * 128 + arow] = av0.z;
        As[(acol + 3) * 128 + arow] = av0.w;
        As[(acol + 4) * 128 + arow] = av1.x;
        As[(acol + 5) * 128 + arow] = av1.y;
        As[(acol + 6) * 128 + arow] = av1.z;
        As[(acol + 7) * 128 + arow] = av1.w;
        float4 bv0 = *(const float4*)(Bb + (size_t)(k0 + brow) * N + bcol);
        float4 bv1 = *(const float4*)(Bb + (size_t)(k0 + brow) * N + bcol + 4);
        *(float4*)&Bs[brow * 128 + bcol]     = bv0;
        *(float4*)&Bs[brow * 128 + bcol + 4] = bv1;
        __syncthreads();
        #pragma unroll
        for (int kk = 0; kk < 16; kk++) {
            float4 a0 = *(const float4*)&As[kk * 128 + tr];
            float4 a1 = *(const float4*)&As[kk * 128 + tr + 4];
            float4 b0 = *(const float4*)&Bs[kk * 128 + tc];
            float4 b1 = *(const float4*)&Bs[kk * 128 + tc + 4];
            float ra[8] = {a0.x, a0.y, a0.z, a0.w, a1.x, a1.y, a1.z, a1.w};
            float rb[8] = {b0.x, b0.y, b0.z, b0.w, b1.x, b1.y, b1.z, b1.w};
            #pragma unroll
            for (int i = 0; i < 8; i++)
                #pragma unroll
                for (int j = 0; j < 8; j++) acc[i][j] += ra[i] * rb[j];
        }
        __syncthreads();
    }

    // ---- epilogue ----
    if (EPI == 0) {
        #pragma unroll
        for (int i = 0; i < 8; i++) {
            int row = tr + i;
            float o[8];
            #pragma unroll
            for (int j = 0; j < 8; j++) o[j] = gelu(acc[i][j] + bb[tc + j]);
            float* crow = C + (size_t)(mt * 128 + row) * N + nt * 128 + tc;
            *(float4*)(crow)     = make_float4(o[0], o[1], o[2], o[3]);
            *(float4*)(crow + 4) = make_float4(o[4], o[5], o[6], o[7]);
        }
    } else {
        #pragma unroll
        for (int i = 0; i < 8; i++)
            #pragma unroll
            for (int j = 0; j < 8; j++)
                hbuf[(tr + i) * 129 + tc + j] = gelu(acc[i][j] + bb[tc + j]);

        if (EPI == 1) {
            float* W3s  = aux;                 // 128*20
            float* b3s  = aux + 2560;          // 20
            float* redf = aux + 2580;          // 256
            int*   redi = (int*)(aux + 2836);  // 256
            for (int i = tid; i < 128 * NATOMS; i += 256) W3s[i] = X0[i];
            if (tid < NATOMS) b3s[tid] = X1[tid];
            __syncthreads();

            int r = tid >> 1, half = tid & 1;
            float lac[10];
            #pragma unroll
            for (int j = 0; j < 10; j++) lac[j] = 0.f;
            for (int k = 0; k < 128; k++) {
                float v = hbuf[r * 129 + k];
                const float* w = W3s + k * NATOMS + half * 10;
                #pragma unroll
                for (int j = 0; j < 10; j++) lac[j] += v * w[j];
            }
            float best = -1e30f; int bidx = 0;
            #pragma unroll
            for (int j = 0; j < 10; j++) {
                int col = half * 10 + j;
                float lg = lac[j] + b3s[col];
                if (lg > best) { best = lg; bidx = col; }
            }
            redf[tid] = best; redi[tid] = bidx;
            __syncthreads();
            if (half == 0) {
                float f0 = redf[tid], f1 = redf[tid + 1];
                int id = (f1 > f0) ? redi[tid + 1] : redi[tid];
                g_ids[mt * 128 + r] = id;
            }
        }
        if (EPI == 2) {
            float* A2s = aux;           // 100*6
            float* a2s = aux + 600;     // 6
            for (int i = tid; i < ENC_H * OUTC; i += 256) A2s[i] = X0[i];
            if (tid < OUTC) a2s[tid] = X1[tid];
            __syncthreads();

            int r = tid >> 1, q0 = (tid & 1) * 3;
            float a3[3] = {0.f, 0.f, 0.f};
            for (int k = 0; k < ENC_H; k++) {
                float v = hbuf[r * 129 + k];
                const float* w = A2s + k * OUTC + q0;
                a3[0] += v * w[0]; a3[1] += v * w[1]; a3[2] += v * w[2];
            }
            float alpha = X2[0];
            int node = mt * 128 + r;
            #pragma unroll
            for (int c = 0; c < 3; c++) {
                int ch = q0 + c;
                float t = gelu(a3[c] + a2s[ch]);
                float u = tanhf(alpha * t) * X3[ch] + X4[ch];
                OUT[(size_t)node * OUTC + ch] = tanhf(u);
            }
        }
    }
}

// ---------------- K8: aggregation -> z, coords ----------------
__global__ void __launch_bounds__(256)
k_agg(const float* __restrict__ b_msg, const float* __restrict__ w_coor,
      const float* __restrict__ coords, float* __restrict__ out_z,
      float* __restrict__ out_coors) {
    __shared__ float TWs[NATOMS * DIM];
    __shared__ float wcs[DIM * 3];
    __shared__ float bms[DIM];
    __shared__ int   hist[8][NATOMS];
    int tid = threadIdx.x;
    for (int i = tid; i < NATOMS * DIM; i += 256) TWs[i] = g_TW[i];
    for (int i = tid; i < DIM * 3; i += 256)      wcs[i] = w_coor[i];
    for (int i = tid; i < DIM; i += 256)          bms[i] = b_msg[i];
    __syncthreads();

    int warp = tid >> 5, lane = tid & 31;
    int* myhist = hist[warp];
    int wglobal = blockIdx.x * 8 + warp;
    int wstride = gridDim.x * 8;
    int d0 = lane * 4;

    for (int node = wglobal; node < NT; node += wstride) {
        if (lane < NATOMS) myhist[lane] = 0;
        __syncwarp();
        int base = node & ~(NPER - 1);
        int deg = 0;
        #pragma unroll
        for (int half = 0; half < 2; half++) {
            int w = lane + half * 32;
            unsigned m = g_mask[(size_t)node * 64 + w];
            deg += __popc(m);
            while (m) {
                int b = __ffs(m) - 1;
                m &= m - 1;
                int id = g_ids[base + w * 32 + b];
                atomicAdd(&myhist[id], 1);
            }
        }
        deg = __reduce_add_sync(0xffffffffu, deg);
        __syncwarp();
        float invdeg = 1.0f / (float)(deg > 0 ? deg : 1);
        int myid = g_ids[node];

        float4 s = make_float4(0.f, 0.f, 0.f, 0.f);
        #pragma unroll
        for (int a = 0; a < NATOMS; a++) {
            float cf = (float)myhist[a];
            float4 t = *(const float4*)&TWs[a * DIM + d0];
            s.x += cf * t.x; s.y += cf * t.y; s.z += cf * t.z; s.w += cf * t.w;
        }
        float4 own = *(const float4*)&TWs[myid * DIM + d0];
        float h0 = gelu(bms[d0 + 0] + own.x + invdeg * s.x);
        float h1 = gelu(bms[d0 + 1] + own.y + invdeg * s.y);
        float h2 = gelu(bms[d0 + 2] + own.z + invdeg * s.z);
        float h3 = gelu(bms[d0 + 3] + own.w + invdeg * s.w);
        *(float4*)&out_z[(size_t)node * DIM + d0] = make_float4(h0, h1, h2, h3);

        float p0 = h0 * wcs[(d0 + 0) * 3 + 0] + h1 * wcs[(d0 + 1) * 3 + 0]
                 + h2 * wcs[(d0 + 2) * 3 + 0] + h3 * wcs[(d0 + 3) * 3 + 0];
        float p1 = h0 * wcs[(d0 + 0) * 3 + 1] + h1 * wcs[(d0 + 1) * 3 + 1]
                 + h2 * wcs[(d0 + 2) * 3 + 1] + h3 * wcs[(d0 + 3) * 3 + 1];
        float p2 = h0 * wcs[(d0 + 0) * 3 + 2] + h1 * wcs[(d0 + 1) * 3 + 2]
                 + h2 * wcs[(d0 + 2) * 3 + 2] + h3 * wcs[(d0 + 3) * 3 + 2];
        #pragma unroll
        for (int o = 16; o > 0; o >>= 1) {
            p0 += __shfl_xor_sync(0xffffffffu, p0, o);
            p1 += __shfl_xor_sync(0xffffffffu, p1, o);
            p2 += __shfl_xor_sync(0xffffffffu, p2, o);
        }
        if (lane == 0) {
            out_coors[(size_t)node * 3 + 0] = coords[(size_t)node * 3 + 0] + tanhf(p0);
            out_coors[(size_t)node * 3 + 1] = coords[(size_t)node * 3 + 1] + tanhf(p1);
            out_coors[(size_t)node * 3 + 2] = coords[(size_t)node * 3 + 2] + tanhf(p2);
        }
    }
}

// ---------------- launch ----------------
#define SMEM0 (4096 * 4)
#define SMEM1 ((4096 + 128 * 129 + 3092) * 4)
#define SMEM2 ((4096 + 128 * 129 + 640) * 4)
extern "C" void kernel_launch(void* const* d_in, const int* in_sizes, int n_in,
                              void* d_out, int out_size) {
    const float* x_res     = (const float*)d_in[0];
    const float* coords    = (const float*)d_in[1];
    const int*   edge_idx  = (const int*)  d_in[2];
    const float* bn_gamma  = (const float*)d_in[4];
    const float* bn_beta   = (const float*)d_in[5];
    const float* W1        = (const float*)d_in[6];
    const float* b1        = (const float*)d_in[7];
    const float* W2        = (const float*)d_in[8];
    const float* b2        = (const float*)d_in[9];
    const float* W3        = (const float*)d_in[10];
    const float* b3        = (const float*)d_in[11];
    const float* embed     = (const float*)d_in[12];
    const float* W_msg     = (const float*)d_in[13];
    const float* b_msg     = (const float*)d_in[14];
    const float* w_coor    = (const float*)d_in[15];
    const float* A1        = (const float*)d_in[16];
    const float* a1        = (const float*)d_in[17];
    const float* A2        = (const float*)d_in[18];
    const float* a2        = (const float*)d_in[19];
    const float* dyt_alpha = (const float*)d_in[20];
    const float* dyt_w     = (const float*)d_in[21];
    const float* dyt_b     = (const float*)d_in[22];
    int E = in_sizes[2] / 2;

    float* out        = (float*)d_out;
    float* out_angles = out;
    float* out_z      = out + (size_t)NT * OUTC;
    float* out_coors  = out_z + (size_t)NT * DIM;

    float* h1p;  cudaGetSymbolAddress((void**)&h1p,  g_h1);
    float* W1fp; cudaGetSymbolAddress((void**)&W1fp, g_W1f);
    float* b1fp; cudaGetSymbolAddress((void**)&b1fp, g_b1f);
    float* A1pp; cudaGetSymbolAddress((void**)&A1pp, g_A1p);
    float* a1pp; cudaGetSymbolAddress((void**)&a1pp, g_a1p);

    cudaFuncSetAttribute((const void*)k_gemm<0>,
                         cudaFuncAttributeMaxDynamicSharedMemorySize, SMEM0);
    cudaFuncSetAttribute((const void*)k_gemm<1>,
                         cudaFuncAttributeMaxDynamicSharedMemorySize, SMEM1);
    cudaFuncSetAttribute((const void*)k_gemm<2>,
                         cudaFuncAttributeMaxDynamicSharedMemorySize, SMEM2);

    k_zero<<<4096, 512>>>();
    k_bn_stats<<<NT / 128, 256>>>(x_res);
    k_fold<<<H1DIM, IN_C>>>(W1, b1, bn_gamma, bn_beta);
    k_tw2<<<320, 256>>>(embed, W_msg);
    k_padA1<<<64, 256>>>(A1, a1);
    k_edges<<<(E + 255) / 256, 256>>>(edge_idx, E);

    // GEMM1: h1 = gelu(xn @ W1f + b1f)   [32768 x 256]
    k_gemm<0><<<dim3(2, 256), 256, SMEM0>>>(
        x_res, W1fp, b1fp, h1p,
        nullptr, nullptr, nullptr, nullptr, nullptr, nullptr, IN_C, H1DIM);
    // GEMM2 fused: h2 tile -> logits -> argmax -> g_ids
    k_gemm<1><<<dim3(1, 256), 256, SMEM1>>>(
        h1p, W2, b2, nullptr,
        W3, b3, nullptr, nullptr, nullptr, nullptr, H1DIM, DIM);
    // z, coords
    k_agg<<<512, 256>>>(b_msg, w_coor, coords, out_z, out_coors);
    // GEMM3 fused: t1 tile -> angles head -> out_angles
    k_gemm<2><<<dim3(1, 256), 256, SMEM2>>>(
        out_z, A1pp, a1pp, nullptr,
        A2, a2, dyt_alpha, dyt_w, dyt_b, out_angles, DIM, 128);
}